// round 14
// baseline (speedup 1.0000x reference)
#include <cuda_runtime.h>
#include <cuda_fp16.h>
#include <mma.h>
#include <cstdint>

using namespace nvcuda;

#define N_NODES 100000
#define D 256
#define MAX_E 3200000

#define SCAN_CHUNK 4096
#define SCAN_BLOCKS ((N_NODES + SCAN_CHUNK - 1) / SCAN_CHUNK)   // 25

// Static device scratch (allocation-free rule; zero-initialized at load)
__device__ __half g_support[(size_t)N_NODES * D];   // X @ W in fp16 (51.2 MB)
__device__ int    g_count [N_NODES];                // re-zeroed by scan2 each run
__device__ int    g_offset[N_NODES];
__device__ int    g_rank  [MAX_E];                  // within-row rank of each edge
__device__ int    g_bsum  [SCAN_BLOCKS];
__device__ uint2  g_csr   [MAX_E];                  // {col, val bits}

// ---------------------------------------------------------------------------
// Side stream + fork/join events, created once at program load (before the
// harness's memory checkpoints; stream/event creation allocates no tracked
// device memory and is legal outside kernel_launch).
// ---------------------------------------------------------------------------
namespace {
struct SideStream {
    cudaStream_t s;
    cudaEvent_t fork, join;
    SideStream() {
        cudaStreamCreateWithFlags(&s, cudaStreamNonBlocking);
        cudaEventCreateWithFlags(&fork, cudaEventDisableTiming);
        cudaEventCreateWithFlags(&join, cudaEventDisableTiming);
    }
};
SideStream g_ss;
}

// ---------------------------------------------------------------------------
// Kernel: fp16 m16n16k16 HMMA GEMM  support = X @ W, fp32 acc, fp16 store.
// 128x128 tile, BK=32, 8 warps (4m x 2n), warp tile 32x64. Conflict-free smem.
// ---------------------------------------------------------------------------
#define AS_LD 40     // halves: 80B row stride -> conflict-free 8-row bank cycle
#define BS_LD 136    // halves: 272B row stride
#define ST_LD 68     // floats

__global__ __launch_bounds__(256) void gemm_kernel(const float* __restrict__ A,
                                                   const float* __restrict__ B) {
    __shared__ __align__(32) union {
        struct {
            __half As[128][AS_LD];
            __half Bs[32][BS_LD];
        } t;
        float staging[128][ST_LD];
    } sh;

    int tid = threadIdx.x;
    int wid  = tid >> 5;
    int warp_m = wid >> 1;
    int warp_n = wid & 1;
    int blockRow = (blockIdx.x >> 1) * 128;
    int blockCol = (blockIdx.x & 1) * 128;

    wmma::fragment<wmma::accumulator, 16, 16, 16, float> acc[2][4];
    #pragma unroll
    for (int i = 0; i < 2; i++)
        #pragma unroll
        for (int j = 0; j < 4; j++)
            wmma::fill_fragment(acc[i][j], 0.0f);

    for (int k0 = 0; k0 < D; k0 += 32) {
        #pragma unroll
        for (int i = 0; i < 4; i++) {
            int f = tid + i * 256;
            int r = f >> 3;
            int c = (f & 7) * 4;
            int row = blockRow + r;
            float4 v = make_float4(0.f, 0.f, 0.f, 0.f);
            if (row < N_NODES)
                v = *reinterpret_cast<const float4*>(&A[(size_t)row * D + k0 + c]);
            __half2 h0 = __float22half2_rn(make_float2(v.x, v.y));
            __half2 h1 = __float22half2_rn(make_float2(v.z, v.w));
            *reinterpret_cast<uint2*>(&sh.t.As[r][c]) =
                make_uint2(*reinterpret_cast<unsigned*>(&h0), *reinterpret_cast<unsigned*>(&h1));
        }
        #pragma unroll
        for (int i = 0; i < 4; i++) {
            int f = tid + i * 256;
            int r = f >> 5;
            int c = (f & 31) * 4;
            float4 v = *reinterpret_cast<const float4*>(&B[(size_t)(k0 + r) * D + blockCol + c]);
            __half2 h0 = __float22half2_rn(make_float2(v.x, v.y));
            __half2 h1 = __float22half2_rn(make_float2(v.z, v.w));
            *reinterpret_cast<uint2*>(&sh.t.Bs[r][c]) =
                make_uint2(*reinterpret_cast<unsigned*>(&h0), *reinterpret_cast<unsigned*>(&h1));
        }
        __syncthreads();

        #pragma unroll
        for (int kk = 0; kk < 32; kk += 16) {
            wmma::fragment<wmma::matrix_a, 16, 16, 16, __half, wmma::row_major> a[2];
            wmma::load_matrix_sync(a[0], &sh.t.As[warp_m * 32][kk], AS_LD);
            wmma::load_matrix_sync(a[1], &sh.t.As[warp_m * 32 + 16][kk], AS_LD);
            #pragma unroll
            for (int j = 0; j < 4; j++) {
                wmma::fragment<wmma::matrix_b, 16, 16, 16, __half, wmma::row_major> b;
                wmma::load_matrix_sync(b, &sh.t.Bs[kk][warp_n * 64 + j * 16], BS_LD);
                wmma::mma_sync(acc[0][j], a[0], b, acc[0][j]);
                wmma::mma_sync(acc[1][j], a[1], b, acc[1][j]);
            }
        }
        __syncthreads();
    }

    #pragma unroll
    for (int phase = 0; phase < 2; phase++) {
        __syncthreads();
        if (warp_n == phase) {
            #pragma unroll
            for (int i = 0; i < 2; i++)
                #pragma unroll
                for (int j = 0; j < 4; j++)
                    wmma::store_matrix_sync(&sh.staging[warp_m * 32 + i * 16][j * 16],
                                            acc[i][j], ST_LD, wmma::mem_row_major);
        }
        __syncthreads();
        #pragma unroll
        for (int it = 0; it < 8; it++) {
            int f = tid + it * 256;
            int r  = f >> 4;
            int c4 = (f & 15) * 4;
            int row = blockRow + r;
            if (row < N_NODES) {
                float4 v = *reinterpret_cast<const float4*>(&sh.staging[r][c4]);
                __half2 h0 = __float22half2_rn(make_float2(v.x, v.y));
                __half2 h1 = __float22half2_rn(make_float2(v.z, v.w));
                uint2 pk = make_uint2(*reinterpret_cast<unsigned*>(&h0),
                                      *reinterpret_cast<unsigned*>(&h1));
                *reinterpret_cast<uint2*>(&g_support[(size_t)row * D + blockCol + phase * 64 + c4]) = pk;
            }
        }
    }
}

// ---------------------------------------------------------------------------
// Histogram + rank capture (4 edges/thread, vectorized).
// ---------------------------------------------------------------------------
__global__ __launch_bounds__(256) void hist_kernel(const int* __restrict__ adj_row, int nE) {
    int i  = blockIdx.x * blockDim.x + threadIdx.x;
    int e0 = i * 4;
    if (e0 + 3 < nE) {
        int4 r4 = *reinterpret_cast<const int4*>(adj_row + e0);
        int k0 = atomicAdd(&g_count[r4.x], 1);
        int k1 = atomicAdd(&g_count[r4.y], 1);
        int k2 = atomicAdd(&g_count[r4.z], 1);
        int k3 = atomicAdd(&g_count[r4.w], 1);
        *reinterpret_cast<int4*>(g_rank + e0) = make_int4(k0, k1, k2, k3);
    } else {
        for (int e = e0; e < nE; e++)
            g_rank[e] = atomicAdd(&g_count[adj_row[e]], 1);
    }
}

// ---------------------------------------------------------------------------
// Scan stage 1: per-block local exclusive scan of 4096 counts (4/thread).
// ---------------------------------------------------------------------------
__global__ __launch_bounds__(1024) void scan1_kernel() {
    __shared__ int sh[1024];
    int b = blockIdx.x, t = threadIdx.x;
    int base = b * SCAN_CHUNK + t * 4;

    int c[4];
    #pragma unroll
    for (int i = 0; i < 4; i++)
        c[i] = (base + i < N_NODES) ? g_count[base + i] : 0;
    int s = c[0] + c[1] + c[2] + c[3];

    sh[t] = s;
    __syncthreads();
    #pragma unroll
    for (int off = 1; off < 1024; off <<= 1) {
        int v = (t >= off) ? sh[t - off] : 0;
        __syncthreads();
        sh[t] += v;
        __syncthreads();
    }

    int run = (t == 0) ? 0 : sh[t - 1];
    #pragma unroll
    for (int i = 0; i < 4; i++) {
        if (base + i < N_NODES) g_offset[base + i] = run;
        run += c[i];
    }
    if (t == 1023) g_bsum[b] = sh[1023];
}

// ---------------------------------------------------------------------------
// Scan stage 2: add block prefix; re-zero g_count for the next replay.
// ---------------------------------------------------------------------------
__global__ __launch_bounds__(1024) void scan2_kernel() {
    __shared__ int s_pre;
    int b = blockIdx.x, t = threadIdx.x;

    if (t < 32) {
        int s = 0;
        for (int i = t; i < b; i += 32) s += g_bsum[i];
        #pragma unroll
        for (int o = 16; o > 0; o >>= 1)
            s += __shfl_down_sync(0xFFFFFFFF, s, o);
        if (t == 0) s_pre = s;
    }
    __syncthreads();
    int pre = s_pre;

    int base = b * SCAN_CHUNK + t * 4;
    #pragma unroll
    for (int i = 0; i < 4; i++) {
        int idx = base + i;
        if (idx < N_NODES) {
            g_offset[idx] += pre;
            g_count[idx] = 0;
        }
    }
}

// ---------------------------------------------------------------------------
// Build: pos = offset[row] + rank[e]  (no atomics), 4 edges per thread.
// ---------------------------------------------------------------------------
__global__ __launch_bounds__(256) void build_kernel(const int* __restrict__ adj_row,
                                                    const int* __restrict__ adj_col,
                                                    const float* __restrict__ adj_val,
                                                    int nE) {
    int i = blockIdx.x * blockDim.x + threadIdx.x;
    int e0 = i * 4;
    if (e0 + 3 < nE) {
        int4   r4 = *reinterpret_cast<const int4*>(adj_row + e0);
        int4   c4 = *reinterpret_cast<const int4*>(adj_col + e0);
        float4 v4 = *reinterpret_cast<const float4*>(adj_val + e0);
        int4   k4 = *reinterpret_cast<const int4*>(g_rank + e0);
        g_csr[g_offset[r4.x] + k4.x] = make_uint2((unsigned)c4.x, __float_as_uint(v4.x));
        g_csr[g_offset[r4.y] + k4.y] = make_uint2((unsigned)c4.y, __float_as_uint(v4.y));
        g_csr[g_offset[r4.z] + k4.z] = make_uint2((unsigned)c4.z, __float_as_uint(v4.z));
        g_csr[g_offset[r4.w] + k4.w] = make_uint2((unsigned)c4.w, __float_as_uint(v4.w));
    } else {
        for (int e = e0; e < nE; e++) {
            g_csr[g_offset[adj_row[e]] + g_rank[e]] =
                make_uint2((unsigned)adj_col[e], __float_as_uint(adj_val[e]));
        }
    }
}

// ---------------------------------------------------------------------------
// CSR SpMM: warp per row, lane owns 8 halves, 8-deep unrolled gather,
// fp32 accumulate, two accumulator banks, bias fused.
// ---------------------------------------------------------------------------
__device__ __forceinline__ void fma_halves(float acc[8], uint4 x, float v) {
    __half2* h = reinterpret_cast<__half2*>(&x);
    #pragma unroll
    for (int i = 0; i < 4; i++) {
        float2 f = __half22float2(h[i]);
        acc[i * 2 + 0] += f.x * v;
        acc[i * 2 + 1] += f.y * v;
    }
}

__global__ __launch_bounds__(256) void spmm_kernel(const float* __restrict__ bias,
                                                   float* __restrict__ out, int nE) {
    int gtid = blockIdx.x * blockDim.x + threadIdx.x;
    int r    = gtid >> 5;
    int lane = gtid & 31;
    if (r >= N_NODES) return;

    int start = g_offset[r];
    int end   = (r == N_NODES - 1) ? nE : g_offset[r + 1];

    float accA[8] = {};
    float accB[8] = {};

    int p = start;
    for (; p + 7 < end; p += 8) {
        uint2 e0 = g_csr[p + 0];
        uint2 e1 = g_csr[p + 1];
        uint2 e2 = g_csr[p + 2];
        uint2 e3 = g_csr[p + 3];
        uint2 e4 = g_csr[p + 4];
        uint2 e5 = g_csr[p + 5];
        uint2 e6 = g_csr[p + 6];
        uint2 e7 = g_csr[p + 7];
        uint4 x0 = *(reinterpret_cast<const uint4*>(g_support + (size_t)e0.x * D) + lane);
        uint4 x1 = *(reinterpret_cast<const uint4*>(g_support + (size_t)e1.x * D) + lane);
        uint4 x2 = *(reinterpret_cast<const uint4*>(g_support + (size_t)e2.x * D) + lane);
        uint4 x3 = *(reinterpret_cast<const uint4*>(g_support + (size_t)e3.x * D) + lane);
        uint4 x4 = *(reinterpret_cast<const uint4*>(g_support + (size_t)e4.x * D) + lane);
        uint4 x5 = *(reinterpret_cast<const uint4*>(g_support + (size_t)e5.x * D) + lane);
        uint4 x6 = *(reinterpret_cast<const uint4*>(g_support + (size_t)e6.x * D) + lane);
        uint4 x7 = *(reinterpret_cast<const uint4*>(g_support + (size_t)e7.x * D) + lane);
        fma_halves(accA, x0, __uint_as_float(e0.y));
        fma_halves(accB, x1, __uint_as_float(e1.y));
        fma_halves(accA, x2, __uint_as_float(e2.y));
        fma_halves(accB, x3, __uint_as_float(e3.y));
        fma_halves(accA, x4, __uint_as_float(e4.y));
        fma_halves(accB, x5, __uint_as_float(e5.y));
        fma_halves(accA, x6, __uint_as_float(e6.y));
        fma_halves(accB, x7, __uint_as_float(e7.y));
    }
    for (; p + 1 < end; p += 2) {
        uint2 e0 = g_csr[p + 0];
        uint2 e1 = g_csr[p + 1];
        uint4 x0 = *(reinterpret_cast<const uint4*>(g_support + (size_t)e0.x * D) + lane);
        uint4 x1 = *(reinterpret_cast<const uint4*>(g_support + (size_t)e1.x * D) + lane);
        fma_halves(accA, x0, __uint_as_float(e0.y));
        fma_halves(accB, x1, __uint_as_float(e1.y));
    }
    if (p < end) {
        uint2 e = g_csr[p];
        uint4 x = *(reinterpret_cast<const uint4*>(g_support + (size_t)e.x * D) + lane);
        fma_halves(accA, x, __uint_as_float(e.y));
    }

    const float4* bp = reinterpret_cast<const float4*>(bias) + lane * 2;
    float4 b0 = bp[0], b1 = bp[1];
    float o0 = accA[0] + accB[0] + b0.x;
    float o1 = accA[1] + accB[1] + b0.y;
    float o2 = accA[2] + accB[2] + b0.z;
    float o3 = accA[3] + accB[3] + b0.w;
    float o4 = accA[4] + accB[4] + b1.x;
    float o5 = accA[5] + accB[5] + b1.y;
    float o6 = accA[6] + accB[6] + b1.z;
    float o7 = accA[7] + accB[7] + b1.w;

    float4* dst = reinterpret_cast<float4*>(out + (size_t)r * D) + lane * 2;
    dst[0] = make_float4(o0, o1, o2, o3);
    dst[1] = make_float4(o4, o5, o6, o7);
}

// ---------------------------------------------------------------------------
// Launch: fork-join graph.
//   main:  gemm ----------------------------\
//   side:  hist -> scan1 -> scan2 -> build --+--> spmm
// ---------------------------------------------------------------------------
extern "C" void kernel_launch(void* const* d_in, const int* in_sizes, int n_in,
                              void* d_out, int out_size) {
    const float* X    = (const float*)d_in[0];
    const int*   arow = (const int*)  d_in[1];
    const int*   acol = (const int*)  d_in[2];
    const float* aval = (const float*)d_in[3];
    const float* W    = (const float*)d_in[4];
    const float* bias = (const float*)d_in[5];
    float*       out  = (float*)d_out;

    int nE = in_sizes[1];
    if (nE > MAX_E) nE = MAX_E;

    int nq = (nE + 3) / 4;
    int eblk = (nq + 255) / 256;

    // Fork: side stream depends on graph root.
    cudaEventRecord(g_ss.fork, 0);
    cudaStreamWaitEvent(g_ss.s, g_ss.fork, 0);

    // Side branch: CSR construction chain.
    hist_kernel <<<eblk, 256, 0, g_ss.s>>>(arow, nE);
    scan1_kernel<<<SCAN_BLOCKS, 1024, 0, g_ss.s>>>();
    scan2_kernel<<<SCAN_BLOCKS, 1024, 0, g_ss.s>>>();
    build_kernel<<<eblk, 256, 0, g_ss.s>>>(arow, acol, aval, nE);
    cudaEventRecord(g_ss.join, g_ss.s);

    // Main branch: dense GEMM (tensor cores).
    int gemm_blocks = (D / 128) * ((N_NODES + 127) / 128);
    gemm_kernel<<<gemm_blocks, 256>>>(X, W);

    // Join, then SpMM.
    cudaStreamWaitEvent(0, g_ss.join, 0);
    long long total_threads = (long long)N_NODES * 32;
    int nblk = (int)((total_threads + 255) / 256);
    spmm_kernel<<<nblk, 256>>>(bias, out, nE);
}